// round 9
// baseline (speedup 1.0000x reference)
#include <cuda_runtime.h>
#include <cuda_fp16.h>
#include <math.h>
#include <stdint.h>

// Problem constants (fixed shapes)
#define NN 50000
#define EE 200000
#define RR 3
#define FF 128
#define HH 256
#define PP 100000
#define NPAIRS (RR*EE + PP)   // 700000
#define NBINS (RR*NN)         // 150000
#define EC 64                 // per-bin edge capacity (Poisson λ=4; max observed ~20)

// scratch layout (float slots) — [zeroed region | persistent region]
#define OFF_SC_OUT 0ull                 // 150000 raw out-degree counts (float)
#define OFF_CURSOR 150000ull            // 150016 ints (post-place: per-bin in-degree)
#define ZERO_FLOATS 300016ull
#define OFF_EDG    300016ull            // 150016*64 uint2 {src, rsqrt(deg_out)} = 19,202,048 slots
#define OFF_XH     19502064ull          // half[N][128] = 3,200,000 slots
#define OFF_AGGH   22702064ull          // half[N][384] = 9,600,000 slots ; reused as z
#define OFF_H1H    32302064ull          // half[N][256] = 6,400,000 slots
#define OFF_U      38702064ull
#define OFF_V      38752064ull
#define OFF_BS1    38802064ull          // 256 floats
#define OFF_BS2    38802320ull          // 128 floats
#define OFF_BT1H   38802448ull          // half[256][384] = 49152 slots
#define OFF_BT2H   38851600ull          // half[384][256] = 49152 slots
#define SCRATCH_TOTAL 38900752ull

__device__ float g_scratch[SCRATCH_TOTAL];

// ================================================================ small kernels
__global__ void zero_kernel() {
    size_t i = (size_t)blockIdx.x * blockDim.x + threadIdx.x;
    if (i < ZERO_FLOATS / 4)
        reinterpret_cast<float4*>(g_scratch)[i] = make_float4(0.f, 0.f, 0.f, 0.f);
}

// fused weight/bias pack
__global__ void pack_kernel(const float* __restrict__ W1, const float* __restrict__ W2,
                            const float* __restrict__ b1, const float* __restrict__ b2) {
    int i = blockIdx.x * blockDim.x + threadIdx.x;
    if (i < HH * RR * FF) {
        int h = i / (RR * FF);
        int k = i - h * (RR * FF);
        __half* bt = reinterpret_cast<__half*>(&g_scratch[OFF_BT1H]);
        bt[(size_t)h * (RR * FF) + k] = __float2half(W1[(size_t)k * HH + h]);
    } else if (i < 2 * HH * RR * FF) {
        int j = i - HH * RR * FF;
        int rf = j / HH;
        int h = j - rf * HH;
        int r = rf >> 7;
        int f = rf & 127;
        __half* bt = reinterpret_cast<__half*>(&g_scratch[OFF_BT2H]);
        bt[(size_t)rf * HH + h] = __float2half(W2[(size_t)r * HH * FF + (size_t)h * FF + f]);
    } else {
        int t = i - 2 * HH * RR * FF;
        if (t < HH) {
            g_scratch[OFF_BS1 + t] = b1[t] + b1[HH + t] + b1[2 * HH + t];
        } else if (t < HH + FF) {
            int h = t - HH;
            g_scratch[OFF_BS2 + h] = b2[h] + b2[FF + h] + b2[2 * FF + h];
        }
    }
}

// x (fp32) -> xh (half); 8 elements per thread
__global__ void xh_kernel(const float* __restrict__ x) {
    int i = blockIdx.x * blockDim.x + threadIdx.x;
    if (i >= NN * FF / 8) return;
    const float4* x4 = reinterpret_cast<const float4*>(x);
    float4 a = x4[2 * i];
    float4 b = x4[2 * i + 1];
    __half2 h0 = __floats2half2_rn(a.x, a.y);
    __half2 h1 = __floats2half2_rn(a.z, a.w);
    __half2 h2 = __floats2half2_rn(b.x, b.y);
    __half2 h3 = __floats2half2_rn(b.z, b.w);
    uint4 o;
    o.x = *reinterpret_cast<unsigned*>(&h0);
    o.y = *reinterpret_cast<unsigned*>(&h1);
    o.z = *reinterpret_cast<unsigned*>(&h2);
    o.w = *reinterpret_cast<unsigned*>(&h3);
    reinterpret_cast<uint4*>(&g_scratch[OFF_XH])[i] = o;
}

// out-degrees only (in-degree comes free from the place cursor)
__global__ void deg_kernel(const int* __restrict__ ei) {
    int i = blockIdx.x * blockDim.x + threadIdx.x;
    if (i >= RR * EE) return;
    int r = i / EE, e = i - r * EE;
    int src = ei[(size_t)r * 2 * EE + e];
    atomicAdd(&g_scratch[OFF_SC_OUT + (size_t)r * NN + src], 1.f);
}

// edge placement into fixed-stride bins; stores {src, rsqrt(deg_out)}
__global__ void place_kernel(const int* __restrict__ ei) {
    int i = blockIdx.x * blockDim.x + threadIdx.x;
    if (i >= RR * EE) return;
    int r = i / EE, e = i - r * EE;
    int src = ei[(size_t)r * 2 * EE + e];
    int dst = ei[(size_t)r * 2 * EE + EE + e];
    float dout = g_scratch[OFF_SC_OUT + (size_t)r * NN + src];
    float so = rsqrtf(fmaxf(dout, 1.f));
    int bin = r * NN + dst;
    int* ip = reinterpret_cast<int*>(g_scratch);
    int slot = atomicAdd(&ip[OFF_CURSOR + bin], 1);
    if (slot >= EC) slot = EC - 1;   // statistically impossible; prevents OOB
    uint2* edg = reinterpret_cast<uint2*>(&g_scratch[OFF_EDG]);
    uint2 rec;
    rec.x = (unsigned)src;
    rec.y = __float_as_uint(so);
    edg[(size_t)bin * EC + slot] = rec;
}

// ================================================================ gather layer 1: warp per (r,dst) bin
__global__ void gather1_kernel() {
    int bin = (blockIdx.x * blockDim.x + threadIdx.x) >> 5;
    int lane = threadIdx.x & 31;
    if (bin >= NBINS) return;
    int r = bin / NN;
    int dst = bin - r * NN;
    const int* ip = reinterpret_cast<const int*>(g_scratch);
    const uint2* edg = reinterpret_cast<const uint2*>(&g_scratch[OFF_EDG]) + (size_t)bin * EC;
    const __half* xh = reinterpret_cast<const __half*>(&g_scratch[OFF_XH]);
    __half* aggh = reinterpret_cast<__half*>(&g_scratch[OFF_AGGH]);

    int cnt = ip[OFF_CURSOR + bin];
    if (cnt > EC) cnt = EC;
    float si = rsqrtf(fmaxf((float)cnt, 1.f));   // dst-side scale (in-degree = cnt)

    float4 a0 = make_float4(0.f, 0.f, 0.f, 0.f);
    float4 a1 = make_float4(0.f, 0.f, 0.f, 0.f);
    int p = 0;
    for (; p + 2 <= cnt; p += 2) {
        uint2 e0 = edg[p];
        uint2 e1 = edg[p + 1];
        float c0 = __uint_as_float(e0.y);
        float c1 = __uint_as_float(e1.y);
        uint2 w0 = *reinterpret_cast<const uint2*>(xh + (size_t)e0.x * FF + lane * 4);
        uint2 w1 = *reinterpret_cast<const uint2*>(xh + (size_t)e1.x * FF + lane * 4);
        float2 f0a = __half22float2(*reinterpret_cast<__half2*>(&w0.x));
        float2 f0b = __half22float2(*reinterpret_cast<__half2*>(&w0.y));
        float2 f1a = __half22float2(*reinterpret_cast<__half2*>(&w1.x));
        float2 f1b = __half22float2(*reinterpret_cast<__half2*>(&w1.y));
        a0.x = fmaf(c0, f0a.x, a0.x); a0.y = fmaf(c0, f0a.y, a0.y);
        a0.z = fmaf(c0, f0b.x, a0.z); a0.w = fmaf(c0, f0b.y, a0.w);
        a1.x = fmaf(c1, f1a.x, a1.x); a1.y = fmaf(c1, f1a.y, a1.y);
        a1.z = fmaf(c1, f1b.x, a1.z); a1.w = fmaf(c1, f1b.y, a1.w);
    }
    if (p < cnt) {
        uint2 e0 = edg[p];
        float c0 = __uint_as_float(e0.y);
        uint2 w0 = *reinterpret_cast<const uint2*>(xh + (size_t)e0.x * FF + lane * 4);
        float2 f0a = __half22float2(*reinterpret_cast<__half2*>(&w0.x));
        float2 f0b = __half22float2(*reinterpret_cast<__half2*>(&w0.y));
        a0.x = fmaf(c0, f0a.x, a0.x); a0.y = fmaf(c0, f0a.y, a0.y);
        a0.z = fmaf(c0, f0b.x, a0.z); a0.w = fmaf(c0, f0b.y, a0.w);
    }
    a0.x = (a0.x + a1.x) * si; a0.y = (a0.y + a1.y) * si;
    a0.z = (a0.z + a1.z) * si; a0.w = (a0.w + a1.w) * si;
    __half2 h01 = __floats2half2_rn(a0.x, a0.y);
    __half2 h23 = __floats2half2_rn(a0.z, a0.w);
    uint2 st2;
    st2.x = *reinterpret_cast<unsigned*>(&h01);
    st2.y = *reinterpret_cast<unsigned*>(&h23);
    *reinterpret_cast<uint2*>(aggh + (size_t)dst * 384 + r * FF + lane * 4) = st2;
}

// ================================================================ gather layer 2 (warp per dst) fused with uv
__global__ void gather2_uv_kernel(const float* __restrict__ Wlin) {
    int dst = (blockIdx.x * blockDim.x + threadIdx.x) >> 5;
    int lane = threadIdx.x & 31;
    if (dst >= NN) return;
    const int* ip = reinterpret_cast<const int*>(g_scratch);
    const __half* zh = reinterpret_cast<const __half*>(&g_scratch[OFF_AGGH]);
    float4 tot = make_float4(0.f, 0.f, 0.f, 0.f);
    #pragma unroll
    for (int r = 0; r < RR; r++) {
        int bin = r * NN + dst;
        const uint2* edg = reinterpret_cast<const uint2*>(&g_scratch[OFF_EDG]) + (size_t)bin * EC;
        int cnt = ip[OFF_CURSOR + bin];
        if (cnt > EC) cnt = EC;
        float si = rsqrtf(fmaxf((float)cnt, 1.f));
        float4 a0 = make_float4(0.f, 0.f, 0.f, 0.f);
        float4 a1 = make_float4(0.f, 0.f, 0.f, 0.f);
        int p = 0;
        for (; p + 2 <= cnt; p += 2) {
            uint2 e0 = edg[p];
            uint2 e1 = edg[p + 1];
            float c0 = __uint_as_float(e0.y);
            float c1 = __uint_as_float(e1.y);
            uint2 w0 = *reinterpret_cast<const uint2*>(zh + (size_t)e0.x * 384 + r * FF + lane * 4);
            uint2 w1 = *reinterpret_cast<const uint2*>(zh + (size_t)e1.x * 384 + r * FF + lane * 4);
            float2 f0a = __half22float2(*reinterpret_cast<__half2*>(&w0.x));
            float2 f0b = __half22float2(*reinterpret_cast<__half2*>(&w0.y));
            float2 f1a = __half22float2(*reinterpret_cast<__half2*>(&w1.x));
            float2 f1b = __half22float2(*reinterpret_cast<__half2*>(&w1.y));
            a0.x = fmaf(c0, f0a.x, a0.x); a0.y = fmaf(c0, f0a.y, a0.y);
            a0.z = fmaf(c0, f0b.x, a0.z); a0.w = fmaf(c0, f0b.y, a0.w);
            a1.x = fmaf(c1, f1a.x, a1.x); a1.y = fmaf(c1, f1a.y, a1.y);
            a1.z = fmaf(c1, f1b.x, a1.z); a1.w = fmaf(c1, f1b.y, a1.w);
        }
        if (p < cnt) {
            uint2 e0 = edg[p];
            float c0 = __uint_as_float(e0.y);
            uint2 w0 = *reinterpret_cast<const uint2*>(zh + (size_t)e0.x * 384 + r * FF + lane * 4);
            float2 f0a = __half22float2(*reinterpret_cast<__half2*>(&w0.x));
            float2 f0b = __half22float2(*reinterpret_cast<__half2*>(&w0.y));
            a0.x = fmaf(c0, f0a.x, a0.x); a0.y = fmaf(c0, f0a.y, a0.y);
            a0.z = fmaf(c0, f0b.x, a0.z); a0.w = fmaf(c0, f0b.y, a0.w);
        }
        tot.x = fmaf(si, a0.x + a1.x, tot.x);
        tot.y = fmaf(si, a0.y + a1.y, tot.y);
        tot.z = fmaf(si, a0.z + a1.z, tot.z);
        tot.w = fmaf(si, a0.w + a1.w, tot.w);
    }
    const float inv3 = (1.f / 3.f);
    float4 bb = *reinterpret_cast<const float4*>(&g_scratch[OFF_BS2 + lane * 4]);
    tot.x = fmaxf((tot.x + bb.x) * inv3, 0.f);
    tot.y = fmaxf((tot.y + bb.y) * inv3, 0.f);
    tot.z = fmaxf((tot.z + bb.z) * inv3, 0.f);
    tot.w = fmaxf((tot.w + bb.w) * inv3, 0.f);
    const float4* wv = reinterpret_cast<const float4*>(Wlin);
    float4 wl = wv[lane];
    float4 wh = wv[32 + lane];
    float su = tot.x * wl.x + tot.y * wl.y + tot.z * wl.z + tot.w * wl.w;
    float sv = tot.x * wh.x + tot.y * wh.y + tot.z * wh.z + tot.w * wh.w;
    #pragma unroll
    for (int o = 16; o > 0; o >>= 1) {
        su += __shfl_down_sync(0xffffffffu, su, o);
        sv += __shfl_down_sync(0xffffffffu, sv, o);
    }
    if (lane == 0) {
        g_scratch[OFF_U + dst] = su;
        g_scratch[OFF_V + dst] = sv;
    }
}

// ================================================================ fp16 tensor-core GEMM (m16n8k16)
#define BM 128
#define BN 64
#define BK 32
#define BKP 40   // +8 halves pad -> conflict-free fragment loads

__device__ __forceinline__ void mma_fp16(float* d, const unsigned* a, const unsigned* b) {
    asm volatile("mma.sync.aligned.m16n8k16.row.col.f32.f16.f16.f32 "
                 "{%0,%1,%2,%3}, {%4,%5,%6,%7}, {%8,%9}, {%0,%1,%2,%3};"
                 : "+f"(d[0]), "+f"(d[1]), "+f"(d[2]), "+f"(d[3])
                 : "r"(a[0]), "r"(a[1]), "r"(a[2]), "r"(a[3]),
                   "r"(b[0]), "r"(b[1]));
}

__global__ __launch_bounds__(256) void gemm_fp16_kernel(
    const __half* __restrict__ A, const __half* __restrict__ Bt,
    const float* __restrict__ bias, __half* __restrict__ C,
    int M, int K, int Ncol, int doRelu, float scale)
{
    __shared__ __half As[BM][BKP];
    __shared__ __half Bs[BN][BKP];

    int tid = threadIdx.x;
    int warp = tid >> 5;
    int lane = tid & 31;
    int wr = warp >> 1;
    int wc = warp & 1;
    int bm = blockIdx.y * BM, bn = blockIdx.x * BN;
    int tg = lane >> 2;
    int tq = lane & 3;

    float acc[2][4][4];
    #pragma unroll
    for (int i = 0; i < 2; i++)
        #pragma unroll
        for (int j = 0; j < 4; j++)
            #pragma unroll
            for (int q = 0; q < 4; q++) acc[i][j][q] = 0.f;

    int ld_row = tid >> 2;
    int ld_c8 = tid & 3;

    for (int k0 = 0; k0 < K; k0 += BK) {
        #pragma unroll
        for (int p = 0; p < 2; p++) {
            int m = bm + p * 64 + ld_row;
            uint4 v = make_uint4(0, 0, 0, 0);
            if (m < M) v = *reinterpret_cast<const uint4*>(A + (size_t)m * K + k0 + ld_c8 * 8);
            *reinterpret_cast<uint4*>(&As[p * 64 + ld_row][ld_c8 * 8]) = v;
        }
        {
            uint4 v = *reinterpret_cast<const uint4*>(Bt + (size_t)(bn + ld_row) * K + k0 + ld_c8 * 8);
            *reinterpret_cast<uint4*>(&Bs[ld_row][ld_c8 * 8]) = v;
        }
        __syncthreads();

        #pragma unroll
        for (int kk = 0; kk < BK; kk += 16) {
            unsigned af[2][4], bf[4][2];
            #pragma unroll
            for (int i = 0; i < 2; i++) {
                int mb = wr * 32 + i * 16;
                af[i][0] = *reinterpret_cast<unsigned*>(&As[mb + tg    ][kk + 2 * tq    ]);
                af[i][1] = *reinterpret_cast<unsigned*>(&As[mb + tg + 8][kk + 2 * tq    ]);
                af[i][2] = *reinterpret_cast<unsigned*>(&As[mb + tg    ][kk + 2 * tq + 8]);
                af[i][3] = *reinterpret_cast<unsigned*>(&As[mb + tg + 8][kk + 2 * tq + 8]);
            }
            #pragma unroll
            for (int j = 0; j < 4; j++) {
                int nb = wc * 32 + j * 8;
                bf[j][0] = *reinterpret_cast<unsigned*>(&Bs[nb + tg][kk + 2 * tq    ]);
                bf[j][1] = *reinterpret_cast<unsigned*>(&Bs[nb + tg][kk + 2 * tq + 8]);
            }
            #pragma unroll
            for (int i = 0; i < 2; i++)
                #pragma unroll
                for (int j = 0; j < 4; j++)
                    mma_fp16(acc[i][j], af[i], bf[j]);
        }
        __syncthreads();
    }

    #pragma unroll
    for (int i = 0; i < 2; i++) {
        #pragma unroll
        for (int j = 0; j < 4; j++) {
            int col = bn + wc * 32 + j * 8 + tq * 2;
            float b0 = 0.f, b1 = 0.f;
            if (bias) { b0 = bias[col]; b1 = bias[col + 1]; }
            #pragma unroll
            for (int h = 0; h < 2; h++) {
                int row = bm + wr * 32 + i * 16 + tg + h * 8;
                if (row < M) {
                    float o0 = (acc[i][j][2 * h + 0] + b0) * scale;
                    float o1 = (acc[i][j][2 * h + 1] + b1) * scale;
                    if (doRelu) { o0 = fmaxf(o0, 0.f); o1 = fmaxf(o1, 0.f); }
                    *reinterpret_cast<__half2*>(C + (size_t)row * Ncol + col) =
                        __floats2half2_rn(o0, o1);
                }
            }
        }
    }
}

// ================================================================ pair head
__global__ void pairs_kernel(const int* __restrict__ ei, const int* __restrict__ np,
                             const float* __restrict__ blin, float* __restrict__ out) {
    int i = blockIdx.x * blockDim.x + threadIdx.x;
    if (i >= NPAIRS) return;
    int src, dst;
    if (i < RR * EE) {
        int r = i / EE, e = i - r * EE;
        src = ei[(size_t)r * 2 * EE + e];
        dst = ei[(size_t)r * 2 * EE + EE + e];
    } else {
        int j = i - RR * EE;
        src = np[2 * j];
        dst = np[2 * j + 1];
    }
    float z = g_scratch[OFF_U + src] + g_scratch[OFF_V + dst] + blin[0];
    out[i] = 1.f / (1.f + expf(-z));
}

// ================================================================ launch
extern "C" void kernel_launch(void* const* d_in, const int* in_sizes, int n_in,
                              void* d_out, int out_size) {
    const float* x    = (const float*)d_in[0];
    const int*   ei   = (const int*)  d_in[1];
    const int*   np   = (const int*)  d_in[2];
    const float* W1   = (const float*)d_in[3];
    const float* b1   = (const float*)d_in[4];
    const float* W2   = (const float*)d_in[5];
    const float* b2   = (const float*)d_in[6];
    const float* Wlin = (const float*)d_in[7];
    const float* blin = (const float*)d_in[8];
    float* out = (float*)d_out;

    void* base = nullptr;
    cudaGetSymbolAddress(&base, g_scratch);
    float* fb = (float*)base;
    __half* aggh = (__half*)(fb + OFF_AGGH);
    __half* h1h  = (__half*)(fb + OFF_H1H);
    __half* bt1h = (__half*)(fb + OFF_BT1H);
    __half* bt2h = (__half*)(fb + OFF_BT2H);
    float* bs1   = fb + OFF_BS1;

    // 1. zero out-degree counters + bin cursors
    zero_kernel<<<(unsigned)((ZERO_FLOATS / 4 + 255) / 256), 256>>>();
    // 2. weight/bias pack + x->half
    pack_kernel<<<(2 * HH * RR * FF + HH + FF + 255) / 256, 256>>>(W1, W2, b1, b2);
    xh_kernel<<<(NN * FF / 8 + 255) / 256, 256>>>(x);
    // 3. out-degrees
    deg_kernel<<<(RR * EE + 255) / 256, 256>>>(ei);
    // 4. edge placement into fixed-stride bins
    place_kernel<<<(RR * EE + 255) / 256, 256>>>(ei);
    // 5. layer-1 gather (warp per bin)
    gather1_kernel<<<(NBINS * 32 + 255) / 256, 256>>>();
    // 6. GEMM1: h1 = relu((agg @ W1 + bs1)/3)
    gemm_fp16_kernel<<<dim3(HH / BN, (NN + BM - 1) / BM), 256>>>(
        aggh, bt1h, bs1, h1h, NN, RR * FF, HH, 1, 1.f / 3.f);
    // 7. GEMM2: z = h1 @ W2P -> reuse aggh
    gemm_fp16_kernel<<<dim3((RR * FF) / BN, (NN + BM - 1) / BM), 256>>>(
        h1h, bt2h, nullptr, aggh, NN, HH, RR * FF, 0, 1.f);
    // 8. layer-2 gather + u/v
    gather2_uv_kernel<<<(NN * 32 + 255) / 256, 256>>>(Wlin);
    // 9. pair outputs
    pairs_kernel<<<(NPAIRS + 255) / 256, 256>>>(ei, np, blin, out);
}

// round 10
// speedup vs baseline: 1.1988x; 1.1988x over previous
#include <cuda_runtime.h>
#include <cuda_fp16.h>
#include <math.h>
#include <stdint.h>

// Problem constants (fixed shapes)
#define NN 50000
#define EE 200000
#define RR 3
#define FF 128
#define HH 256
#define PP 100000
#define NPAIRS (RR*EE + PP)   // 700000
#define NBINS (RR*NN)         // 150000

// scratch layout (float slots) — [zeroed region | persistent region]
#define OFF_SC_OUT 0ull                 // 150000 raw out-degree counts
#define OFF_SC_IN  150000ull            // 150000 raw in-degree counts
#define OFF_CURSOR 300000ull            // 150016 ints
#define ZERO_FLOATS 450016ull
#define OFF_OFFSET 450016ull            // 150016 ints
#define OFF_BLKSUM 600032ull            // 256 ints
#define OFF_EDG    600288ull            // 600000 x uint2 {src, scale} = 1,200,000 slots
#define OFF_XH     1800288ull           // half[N][128] = 3,200,000 slots
#define OFF_AGGH   5000288ull           // half[N][384] = 9,600,000 slots ; reused as z
#define OFF_H1H    14600288ull          // half[N][256] = 6,400,000 slots
#define OFF_U      21000288ull
#define OFF_V      21050288ull
#define OFF_BS1    21100288ull          // 256 floats
#define OFF_BS2    21100544ull          // 128 floats
#define OFF_BT1H   21100672ull          // half[256][384] = 49152 slots
#define OFF_BT2H   21149824ull          // half[384][256] = 49152 slots
#define SCRATCH_TOTAL 21198976ull

__device__ float g_scratch[SCRATCH_TOTAL];

// ================================================================ small kernels
__global__ void zero_kernel() {
    size_t i = (size_t)blockIdx.x * blockDim.x + threadIdx.x;
    if (i < ZERO_FLOATS / 4)
        reinterpret_cast<float4*>(g_scratch)[i] = make_float4(0.f, 0.f, 0.f, 0.f);
}

// fused weight/bias pack
__global__ void pack_kernel(const float* __restrict__ W1, const float* __restrict__ W2,
                            const float* __restrict__ b1, const float* __restrict__ b2) {
    int i = blockIdx.x * blockDim.x + threadIdx.x;
    if (i < HH * RR * FF) {
        int h = i / (RR * FF);
        int k = i - h * (RR * FF);
        __half* bt = reinterpret_cast<__half*>(&g_scratch[OFF_BT1H]);
        bt[(size_t)h * (RR * FF) + k] = __float2half(W1[(size_t)k * HH + h]);
    } else if (i < 2 * HH * RR * FF) {
        int j = i - HH * RR * FF;
        int rf = j / HH;
        int h = j - rf * HH;
        int r = rf >> 7;
        int f = rf & 127;
        __half* bt = reinterpret_cast<__half*>(&g_scratch[OFF_BT2H]);
        bt[(size_t)rf * HH + h] = __float2half(W2[(size_t)r * HH * FF + (size_t)h * FF + f]);
    } else {
        int t = i - 2 * HH * RR * FF;
        if (t < HH) {
            g_scratch[OFF_BS1 + t] = b1[t] + b1[HH + t] + b1[2 * HH + t];
        } else if (t < HH + FF) {
            int h = t - HH;
            g_scratch[OFF_BS2 + h] = b2[h] + b2[FF + h] + b2[2 * FF + h];
        }
    }
}

// x (fp32) -> xh (half)
__global__ void xh_kernel(const float* __restrict__ x) {
    int i = blockIdx.x * blockDim.x + threadIdx.x;
    if (i >= NN * FF / 8) return;
    const float4* x4 = reinterpret_cast<const float4*>(x);
    float4 a = x4[2 * i];
    float4 b = x4[2 * i + 1];
    __half2 h0 = __floats2half2_rn(a.x, a.y);
    __half2 h1 = __floats2half2_rn(a.z, a.w);
    __half2 h2 = __floats2half2_rn(b.x, b.y);
    __half2 h3 = __floats2half2_rn(b.z, b.w);
    uint4 o;
    o.x = *reinterpret_cast<unsigned*>(&h0);
    o.y = *reinterpret_cast<unsigned*>(&h1);
    o.z = *reinterpret_cast<unsigned*>(&h2);
    o.w = *reinterpret_cast<unsigned*>(&h3);
    reinterpret_cast<uint4*>(&g_scratch[OFF_XH])[i] = o;
}

__global__ void deg_kernel(const int* __restrict__ ei) {
    int i = blockIdx.x * blockDim.x + threadIdx.x;
    if (i >= RR * EE) return;
    int r = i / EE, e = i - r * EE;
    int src = ei[(size_t)r * 2 * EE + e];
    int dst = ei[(size_t)r * 2 * EE + EE + e];
    atomicAdd(&g_scratch[OFF_SC_OUT + (size_t)r * NN + src], 1.f);
    atomicAdd(&g_scratch[OFF_SC_IN  + (size_t)r * NN + dst], 1.f);
}

#define SCAN_B 1024
#define SCAN_NBLK ((NBINS + SCAN_B - 1) / SCAN_B)   // 147

__global__ void scanA_kernel() {
    __shared__ int sm[SCAN_B];
    int tid = threadIdx.x;
    int i = blockIdx.x * SCAN_B + tid;
    int v = (i < NBINS) ? (int)g_scratch[OFF_SC_IN + i] : 0;
    sm[tid] = v;
    __syncthreads();
    for (int off = 1; off < SCAN_B; off <<= 1) {
        int t = (tid >= off) ? sm[tid - off] : 0;
        __syncthreads();
        sm[tid] += t;
        __syncthreads();
    }
    if (i < NBINS)
        reinterpret_cast<int*>(g_scratch)[OFF_OFFSET + i] = sm[tid] - v;
    if (tid == SCAN_B - 1)
        reinterpret_cast<int*>(g_scratch)[OFF_BLKSUM + blockIdx.x] = sm[tid];
}

__global__ void scanB_kernel() {
    __shared__ int sm[256];
    int tid = threadIdx.x;
    int* bs = reinterpret_cast<int*>(g_scratch) + OFF_BLKSUM;
    int v = (tid < SCAN_NBLK) ? bs[tid] : 0;
    sm[tid] = v;
    __syncthreads();
    for (int off = 1; off < 256; off <<= 1) {
        int t = (tid >= off) ? sm[tid - off] : 0;
        __syncthreads();
        sm[tid] += t;
        __syncthreads();
    }
    if (tid < SCAN_NBLK) bs[tid] = sm[tid] - v;
}

__global__ void scanC_kernel() {
    int i = blockIdx.x * blockDim.x + threadIdx.x;
    if (i >= NBINS) return;
    int* ip = reinterpret_cast<int*>(g_scratch);
    ip[OFF_OFFSET + i] += ip[OFF_BLKSUM + i / SCAN_B];
}

// edge placement: CSR by (r,dst), rsqrt-scales computed inline
__global__ void place_kernel(const int* __restrict__ ei) {
    int i = blockIdx.x * blockDim.x + threadIdx.x;
    if (i >= RR * EE) return;
    int r = i / EE, e = i - r * EE;
    int src = ei[(size_t)r * 2 * EE + e];
    int dst = ei[(size_t)r * 2 * EE + EE + e];
    float dout = g_scratch[OFF_SC_OUT + (size_t)r * NN + src];
    float din  = g_scratch[OFF_SC_IN  + (size_t)r * NN + dst];
    float s = rsqrtf(fmaxf(dout, 1.f)) * rsqrtf(fmaxf(din, 1.f));
    int bin = r * NN + dst;
    int* ip = reinterpret_cast<int*>(g_scratch);
    int pos = ip[OFF_OFFSET + bin] + atomicAdd(&ip[OFF_CURSOR + bin], 1);
    uint2* edg = reinterpret_cast<uint2*>(&g_scratch[OFF_EDG]);
    uint2 rec;
    rec.x = (unsigned)src;
    rec.y = __float_as_uint(s);
    edg[pos] = rec;
}

// ================================================================ gather layer 1 (half in, fp32 accum, half out)
__global__ void gather1_kernel() {
    int dst = (blockIdx.x * blockDim.x + threadIdx.x) >> 5;
    int lane = threadIdx.x & 31;
    if (dst >= NN) return;
    const int* ip = reinterpret_cast<const int*>(g_scratch);
    const uint2* edg = reinterpret_cast<const uint2*>(&g_scratch[OFF_EDG]);
    const __half* xh = reinterpret_cast<const __half*>(&g_scratch[OFF_XH]);
    __half* aggh = reinterpret_cast<__half*>(&g_scratch[OFF_AGGH]);
    #pragma unroll
    for (int r = 0; r < RR; r++) {
        int bin = r * NN + dst;
        int st = ip[OFF_OFFSET + bin];
        int cnt = ip[OFF_CURSOR + bin];
        float4 a0 = make_float4(0.f, 0.f, 0.f, 0.f);
        float4 a1 = make_float4(0.f, 0.f, 0.f, 0.f);
        int p = 0;
        for (; p + 2 <= cnt; p += 2) {
            uint2 e0 = edg[st + p];
            uint2 e1 = edg[st + p + 1];
            float c0 = __uint_as_float(e0.y);
            float c1 = __uint_as_float(e1.y);
            uint2 w0 = *reinterpret_cast<const uint2*>(xh + (size_t)e0.x * FF + lane * 4);
            uint2 w1 = *reinterpret_cast<const uint2*>(xh + (size_t)e1.x * FF + lane * 4);
            float2 f0a = __half22float2(*reinterpret_cast<__half2*>(&w0.x));
            float2 f0b = __half22float2(*reinterpret_cast<__half2*>(&w0.y));
            float2 f1a = __half22float2(*reinterpret_cast<__half2*>(&w1.x));
            float2 f1b = __half22float2(*reinterpret_cast<__half2*>(&w1.y));
            a0.x = fmaf(c0, f0a.x, a0.x); a0.y = fmaf(c0, f0a.y, a0.y);
            a0.z = fmaf(c0, f0b.x, a0.z); a0.w = fmaf(c0, f0b.y, a0.w);
            a1.x = fmaf(c1, f1a.x, a1.x); a1.y = fmaf(c1, f1a.y, a1.y);
            a1.z = fmaf(c1, f1b.x, a1.z); a1.w = fmaf(c1, f1b.y, a1.w);
        }
        if (p < cnt) {
            uint2 e0 = edg[st + p];
            float c0 = __uint_as_float(e0.y);
            uint2 w0 = *reinterpret_cast<const uint2*>(xh + (size_t)e0.x * FF + lane * 4);
            float2 f0a = __half22float2(*reinterpret_cast<__half2*>(&w0.x));
            float2 f0b = __half22float2(*reinterpret_cast<__half2*>(&w0.y));
            a0.x = fmaf(c0, f0a.x, a0.x); a0.y = fmaf(c0, f0a.y, a0.y);
            a0.z = fmaf(c0, f0b.x, a0.z); a0.w = fmaf(c0, f0b.y, a0.w);
        }
        a0.x += a1.x; a0.y += a1.y; a0.z += a1.z; a0.w += a1.w;
        __half2 h01 = __floats2half2_rn(a0.x, a0.y);
        __half2 h23 = __floats2half2_rn(a0.z, a0.w);
        uint2 st2;
        st2.x = *reinterpret_cast<unsigned*>(&h01);
        st2.y = *reinterpret_cast<unsigned*>(&h23);
        *reinterpret_cast<uint2*>(aggh + (size_t)dst * 384 + r * FF + lane * 4) = st2;
    }
}

// ================================================================ gather layer 2 (half in) fused with uv
__global__ void gather2_uv_kernel(const float* __restrict__ Wlin) {
    int dst = (blockIdx.x * blockDim.x + threadIdx.x) >> 5;
    int lane = threadIdx.x & 31;
    if (dst >= NN) return;
    const int* ip = reinterpret_cast<const int*>(g_scratch);
    const uint2* edg = reinterpret_cast<const uint2*>(&g_scratch[OFF_EDG]);
    const __half* zh = reinterpret_cast<const __half*>(&g_scratch[OFF_AGGH]);
    float4 a0 = make_float4(0.f, 0.f, 0.f, 0.f);
    float4 a1 = make_float4(0.f, 0.f, 0.f, 0.f);
    #pragma unroll
    for (int r = 0; r < RR; r++) {
        int bin = r * NN + dst;
        int st = ip[OFF_OFFSET + bin];
        int cnt = ip[OFF_CURSOR + bin];
        int p = 0;
        for (; p + 2 <= cnt; p += 2) {
            uint2 e0 = edg[st + p];
            uint2 e1 = edg[st + p + 1];
            float c0 = __uint_as_float(e0.y);
            float c1 = __uint_as_float(e1.y);
            uint2 w0 = *reinterpret_cast<const uint2*>(zh + (size_t)e0.x * 384 + r * FF + lane * 4);
            uint2 w1 = *reinterpret_cast<const uint2*>(zh + (size_t)e1.x * 384 + r * FF + lane * 4);
            float2 f0a = __half22float2(*reinterpret_cast<__half2*>(&w0.x));
            float2 f0b = __half22float2(*reinterpret_cast<__half2*>(&w0.y));
            float2 f1a = __half22float2(*reinterpret_cast<__half2*>(&w1.x));
            float2 f1b = __half22float2(*reinterpret_cast<__half2*>(&w1.y));
            a0.x = fmaf(c0, f0a.x, a0.x); a0.y = fmaf(c0, f0a.y, a0.y);
            a0.z = fmaf(c0, f0b.x, a0.z); a0.w = fmaf(c0, f0b.y, a0.w);
            a1.x = fmaf(c1, f1a.x, a1.x); a1.y = fmaf(c1, f1a.y, a1.y);
            a1.z = fmaf(c1, f1b.x, a1.z); a1.w = fmaf(c1, f1b.y, a1.w);
        }
        if (p < cnt) {
            uint2 e0 = edg[st + p];
            float c0 = __uint_as_float(e0.y);
            uint2 w0 = *reinterpret_cast<const uint2*>(zh + (size_t)e0.x * 384 + r * FF + lane * 4);
            float2 f0a = __half22float2(*reinterpret_cast<__half2*>(&w0.x));
            float2 f0b = __half22float2(*reinterpret_cast<__half2*>(&w0.y));
            a0.x = fmaf(c0, f0a.x, a0.x); a0.y = fmaf(c0, f0a.y, a0.y);
            a0.z = fmaf(c0, f0b.x, a0.z); a0.w = fmaf(c0, f0b.y, a0.w);
        }
    }
    a0.x += a1.x; a0.y += a1.y; a0.z += a1.z; a0.w += a1.w;
    const float inv3 = (1.f / 3.f);
    float4 bb = *reinterpret_cast<const float4*>(&g_scratch[OFF_BS2 + lane * 4]);
    a0.x = fmaxf((a0.x + bb.x) * inv3, 0.f);
    a0.y = fmaxf((a0.y + bb.y) * inv3, 0.f);
    a0.z = fmaxf((a0.z + bb.z) * inv3, 0.f);
    a0.w = fmaxf((a0.w + bb.w) * inv3, 0.f);
    const float4* wv = reinterpret_cast<const float4*>(Wlin);
    float4 wl = wv[lane];
    float4 wh = wv[32 + lane];
    float su = a0.x * wl.x + a0.y * wl.y + a0.z * wl.z + a0.w * wl.w;
    float sv = a0.x * wh.x + a0.y * wh.y + a0.z * wh.z + a0.w * wh.w;
    #pragma unroll
    for (int o = 16; o > 0; o >>= 1) {
        su += __shfl_down_sync(0xffffffffu, su, o);
        sv += __shfl_down_sync(0xffffffffu, sv, o);
    }
    if (lane == 0) {
        g_scratch[OFF_U + dst] = su;
        g_scratch[OFF_V + dst] = sv;
    }
}

// ================================================================ fp16 tensor-core GEMM
// BM=128, BN=128, BK=32; 256 threads; cp.async double-buffered
#define BM 128
#define BN 128
#define BK 32
#define BKP 40   // +8 halves pad -> conflict-free fragment loads

__device__ __forceinline__ void mma_fp16(float* d, const unsigned* a, const unsigned* b) {
    asm volatile("mma.sync.aligned.m16n8k16.row.col.f32.f16.f16.f32 "
                 "{%0,%1,%2,%3}, {%4,%5,%6,%7}, {%8,%9}, {%0,%1,%2,%3};"
                 : "+f"(d[0]), "+f"(d[1]), "+f"(d[2]), "+f"(d[3])
                 : "r"(a[0]), "r"(a[1]), "r"(a[2]), "r"(a[3]),
                   "r"(b[0]), "r"(b[1]));
}

__device__ __forceinline__ uint32_t smem_cast(const void* p) {
    uint32_t a;
    asm("{ .reg .u64 t; cvta.to.shared.u64 t, %1; cvt.u32.u64 %0, t; }" : "=r"(a) : "l"(p));
    return a;
}

__device__ __forceinline__ void cp_async16(uint32_t dst, const void* src, int src_bytes) {
    asm volatile("cp.async.ca.shared.global [%0], [%1], 16, %2;"
                 :: "r"(dst), "l"(src), "r"(src_bytes) : "memory");
}
#define CP_COMMIT() asm volatile("cp.async.commit_group;" ::: "memory")
#define CP_WAIT1()  asm volatile("cp.async.wait_group 1;" ::: "memory")
#define CP_WAIT0()  asm volatile("cp.async.wait_group 0;" ::: "memory")

__global__ __launch_bounds__(256) void gemm_fp16_kernel(
    const __half* __restrict__ A, const __half* __restrict__ Bt,
    const float* __restrict__ bias, __half* __restrict__ C,
    int M, int K, int Ncol, int doRelu, float scale)
{
    __shared__ __half As[2][BM][BKP];
    __shared__ __half Bs[2][BN][BKP];

    int tid = threadIdx.x;
    int warp = tid >> 5;
    int lane = tid & 31;
    int wr = warp >> 1;        // 0..3 -> m offset 32*wr
    int wc = warp & 1;         // 0..1 -> n offset 64*wc
    int bm = blockIdx.y * BM, bn = blockIdx.x * BN;
    int tg = lane >> 2;        // 0..7
    int tq = lane & 3;         // 0..3

    float acc[2][8][4];
    #pragma unroll
    for (int i = 0; i < 2; i++)
        #pragma unroll
        for (int j = 0; j < 8; j++)
            #pragma unroll
            for (int q = 0; q < 4; q++) acc[i][j][q] = 0.f;

    uint32_t as_base = smem_cast(&As[0][0][0]);
    uint32_t bs_base = smem_cast(&Bs[0][0][0]);
    const uint32_t BUFB = BM * BKP * 2;   // 10240 bytes per buffer (same for A and B)

    int nT = K / BK;

    // ---- tile loader: 512 16B chunks each for A and B, 2+2 per thread
    #define LOAD_TILE(k0, buf) do {                                              \
        _Pragma("unroll")                                                        \
        for (int it = 0; it < 2; it++) {                                         \
            int ch = tid + it * 256;                                             \
            int row = ch >> 2, c8 = ch & 3;                                      \
            int m = bm + row;                                                    \
            int mc = (m < M) ? m : 0;                                            \
            cp_async16(as_base + (buf) * BUFB + row * (BKP * 2) + c8 * 16,       \
                       A + (size_t)mc * K + (k0) + c8 * 8, (m < M) ? 16 : 0);    \
        }                                                                        \
        _Pragma("unroll")                                                        \
        for (int it = 0; it < 2; it++) {                                         \
            int ch = tid + it * 256;                                             \
            int row = ch >> 2, c8 = ch & 3;                                      \
            cp_async16(bs_base + (buf) * BUFB + row * (BKP * 2) + c8 * 16,       \
                       Bt + (size_t)(bn + row) * K + (k0) + c8 * 8, 16);         \
        }                                                                        \
    } while (0)

    // prologue
    LOAD_TILE(0, 0);
    CP_COMMIT();

    for (int t = 0; t < nT; t++) {
        int buf = t & 1;
        if (t + 1 < nT) {
            LOAD_TILE((t + 1) * BK, buf ^ 1);
            CP_COMMIT();
            CP_WAIT1();
        } else {
            CP_WAIT0();
        }
        __syncthreads();

        #pragma unroll
        for (int kk = 0; kk < BK; kk += 16) {
            unsigned af[2][4], bf[8][2];
            #pragma unroll
            for (int i = 0; i < 2; i++) {
                int mb = wr * 32 + i * 16;
                af[i][0] = *reinterpret_cast<unsigned*>(&As[buf][mb + tg    ][kk + 2 * tq    ]);
                af[i][1] = *reinterpret_cast<unsigned*>(&As[buf][mb + tg + 8][kk + 2 * tq    ]);
                af[i][2] = *reinterpret_cast<unsigned*>(&As[buf][mb + tg    ][kk + 2 * tq + 8]);
                af[i][3] = *reinterpret_cast<unsigned*>(&As[buf][mb + tg + 8][kk + 2 * tq + 8]);
            }
            #pragma unroll
            for (int j = 0; j < 8; j++) {
                int nb = wc * 64 + j * 8;
                bf[j][0] = *reinterpret_cast<unsigned*>(&Bs[buf][nb + tg][kk + 2 * tq    ]);
                bf[j][1] = *reinterpret_cast<unsigned*>(&Bs[buf][nb + tg][kk + 2 * tq + 8]);
            }
            #pragma unroll
            for (int i = 0; i < 2; i++)
                #pragma unroll
                for (int j = 0; j < 8; j++)
                    mma_fp16(acc[i][j], af[i], bf[j]);
        }
        __syncthreads();   // guard: next iteration's cp.async overwrites this buf
    }

    // epilogue
    #pragma unroll
    for (int i = 0; i < 2; i++) {
        #pragma unroll
        for (int j = 0; j < 8; j++) {
            int col = bn + wc * 64 + j * 8 + tq * 2;
            float b0 = 0.f, b1 = 0.f;
            if (bias) { b0 = bias[col]; b1 = bias[col + 1]; }
            #pragma unroll
            for (int h = 0; h < 2; h++) {
                int row = bm + wr * 32 + i * 16 + tg + h * 8;
                if (row < M) {
                    float o0 = (acc[i][j][2 * h + 0] + b0) * scale;
                    float o1 = (acc[i][j][2 * h + 1] + b1) * scale;
                    if (doRelu) { o0 = fmaxf(o0, 0.f); o1 = fmaxf(o1, 0.f); }
                    *reinterpret_cast<__half2*>(C + (size_t)row * Ncol + col) =
                        __floats2half2_rn(o0, o1);
                }
            }
        }
    }
}

// ================================================================ pair head
__global__ void pairs_kernel(const int* __restrict__ ei, const int* __restrict__ np,
                             const float* __restrict__ blin, float* __restrict__ out) {
    int i = blockIdx.x * blockDim.x + threadIdx.x;
    if (i >= NPAIRS) return;
    int src, dst;
    if (i < RR * EE) {
        int r = i / EE, e = i - r * EE;
        src = ei[(size_t)r * 2 * EE + e];
        dst = ei[(size_t)r * 2 * EE + EE + e];
    } else {
        int j = i - RR * EE;
        src = np[2 * j];
        dst = np[2 * j + 1];
    }
    float z = g_scratch[OFF_U + src] + g_scratch[OFF_V + dst] + blin[0];
    out[i] = 1.f / (1.f + expf(-z));
}

// ================================================================ launch
extern "C" void kernel_launch(void* const* d_in, const int* in_sizes, int n_in,
                              void* d_out, int out_size) {
    const float* x    = (const float*)d_in[0];
    const int*   ei   = (const int*)  d_in[1];
    const int*   np   = (const int*)  d_in[2];
    const float* W1   = (const float*)d_in[3];
    const float* b1   = (const float*)d_in[4];
    const float* W2   = (const float*)d_in[5];
    const float* b2   = (const float*)d_in[6];
    const float* Wlin = (const float*)d_in[7];
    const float* blin = (const float*)d_in[8];
    float* out = (float*)d_out;

    void* base = nullptr;
    cudaGetSymbolAddress(&base, g_scratch);
    float* fb = (float*)base;
    __half* aggh = (__half*)(fb + OFF_AGGH);
    __half* h1h  = (__half*)(fb + OFF_H1H);
    __half* bt1h = (__half*)(fb + OFF_BT1H);
    __half* bt2h = (__half*)(fb + OFF_BT2H);
    float* bs1   = fb + OFF_BS1;

    // 1. zero scales + cursors
    zero_kernel<<<(unsigned)((ZERO_FLOATS / 4 + 255) / 256), 256>>>();
    // 2. weight/bias pack + x->half
    pack_kernel<<<(2 * HH * RR * FF + HH + FF + 255) / 256, 256>>>(W1, W2, b1, b2);
    xh_kernel<<<(NN * FF / 8 + 255) / 256, 256>>>(x);
    // 3. degrees
    deg_kernel<<<(RR * EE + 255) / 256, 256>>>(ei);
    // 4. CSR offsets
    scanA_kernel<<<SCAN_NBLK, SCAN_B>>>();
    scanB_kernel<<<1, 256>>>();
    scanC_kernel<<<(NBINS + 255) / 256, 256>>>();
    // 5. edge placement (rsqrt folded)
    place_kernel<<<(RR * EE + 255) / 256, 256>>>(ei);
    // 6. layer-1 gather
    gather1_kernel<<<(NN * 32 + 255) / 256, 256>>>();
    // 7. GEMM1: h1 = relu((agg @ W1 + bs1)/3)  [50000,384]x[384,256]
    gemm_fp16_kernel<<<dim3(HH / BN, (NN + BM - 1) / BM), 256>>>(
        aggh, bt1h, bs1, h1h, NN, RR * FF, HH, 1, 1.f / 3.f);
    // 8. GEMM2: z = h1 @ W2P  [50000,256]x[256,384] -> reuse aggh
    gemm_fp16_kernel<<<dim3((RR * FF) / BN, (NN + BM - 1) / BM), 256>>>(
        h1h, bt2h, nullptr, aggh, NN, HH, RR * FF, 0, 1.f);
    // 9. layer-2 gather + u/v
    gather2_uv_kernel<<<(NN * 32 + 255) / 256, 256>>>(Wlin);
    // 10. pair outputs
    pairs_kernel<<<(NPAIRS + 255) / 256, 256>>>(ei, np, blin, out);
}